// round 16
// baseline (speedup 1.0000x reference)
#include <cuda_runtime.h>
#include <cuda_bf16.h>
#include <cstdint>

#define B_TOT  8192
#define NN     82
#define HH     10
#define NOUT   5
#define TSTEPS 3
#define GB     6            // batches per block
#define BD     256          // 8 warps; act threads = 41*6 = 246 (2 nodes/thread)
#define NROW   12
#define MHALF  41
#define RS     52           // row stride in 32-bit words for adj/X tiles (104 bf16)

// ---- shared memory word (float) offsets ----
#define SM_AIH 0                 // adj in  hi : 96 x 52 words
#define SM_AIL 4992              // adj in  lo
#define SM_AOH 9984              // adj out hi
#define SM_AOL 14976             // adj out lo
#define SM_XHI 19968             // X hi : 64 x 52 words
#define SM_XLO 23296             // X lo
#define SM_AV  26624             // av : 6*82*22 floats
#define SM_ND  37448             // node states : 82*6*12 floats
#define SM_TOTALW 43352          // 173408 bytes

// dense weights + biases in constant memory
__constant__ float c_w3w[200];
__constant__ float c_w4w[200];
__constant__ float c_w5w[200];
__constant__ float c_wout[100];
__constant__ float c_w3u[100];
__constant__ float c_w5u[100];
__constant__ float c_b3w[10];
__constant__ float c_b3u[10];
__constant__ float c_b4w[10];
__constant__ float c_b5w[10];
__constant__ float c_b5u[10];
__constant__ float c_bout[5];

union F4U { float4 v; unsigned long long u[2]; float f[4]; };
union F2U { unsigned long long u; float2 f; };

__device__ __forceinline__ unsigned long long pack2(float a, float b) {
    unsigned long long r;
    asm("mov.b64 %0, {%1, %2};" : "=l"(r) : "f"(a), "f"(b));
    return r;
}
__device__ __forceinline__ void fma2(unsigned long long& acc,
                                     unsigned long long a, unsigned long long b) {
    asm("fma.rn.f32x2 %0, %1, %2, %0;" : "+l"(acc) : "l"(a), "l"(b));
}
__device__ __forceinline__ float hsum2(unsigned long long p) {
    F2U u; u.u = p; return u.f.x + u.f.y;
}
__device__ __forceinline__ float sigmoid_f(float v) {
    return __fdividef(1.0f, 1.0f + __expf(-v));
}
__device__ __forceinline__ float tanh_f(float v) {
    return __fdividef(2.0f, 1.0f + __expf(-2.0f * v)) - 1.0f;
}
__device__ __forceinline__ void load10(const float* p, unsigned long long* d) {
    F4U q0, q1; F2U q2;
    q0.v = *(const float4*)(p);
    q1.v = *(const float4*)(p + 4);
    q2.f = *(const float2*)(p + 8);
    d[0] = q0.u[0]; d[1] = q0.u[1]; d[2] = q1.u[0]; d[3] = q1.u[1]; d[4] = q2.u;
}
__device__ __forceinline__ void dot20x2c(const float* wrow,
                                         const unsigned long long* av0,
                                         const unsigned long long* av1,
                                         float& r0, float& r1) {
    unsigned long long a0 = 0ULL, a1 = 0ULL;
    #pragma unroll
    for (int q = 0; q < 5; q++) {
        F4U w_;
        w_.v = *(const float4*)(wrow + 4 * q);
        fma2(a0, w_.u[0], av0[2 * q]);
        fma2(a0, w_.u[1], av0[2 * q + 1]);
        fma2(a1, w_.u[0], av1[2 * q]);
        fma2(a1, w_.u[1], av1[2 * q + 1]);
    }
    r0 = hsum2(a0);
    r1 = hsum2(a1);
}
__device__ __forceinline__ void dot10x2c(const float* urow,
                                         const unsigned long long* v0,
                                         const unsigned long long* v1,
                                         float& r0, float& r1) {
    unsigned long long a0 = 0ULL, a1 = 0ULL;
    #pragma unroll
    for (int p = 0; p < 5; p++) {
        F2U w; w.f = *(const float2*)(urow + 2 * p);
        fma2(a0, w.u, v0[p]);
        fma2(a1, w.u, v1[p]);
    }
    r0 = hsum2(a0);
    r1 = hsum2(a1);
}

// bf16 hi/lo split of two floats -> two packed words
__device__ __forceinline__ void bsplit2(float f0, float f1, uint32_t& hw, uint32_t& lw) {
    __nv_bfloat16 h0 = __float2bfloat16(f0);
    __nv_bfloat16 h1 = __float2bfloat16(f1);
    __nv_bfloat16 l0 = __float2bfloat16(f0 - __bfloat162float(h0));
    __nv_bfloat16 l1 = __float2bfloat16(f1 - __bfloat162float(h1));
    __nv_bfloat162 hp; hp.x = h0; hp.y = h1;
    __nv_bfloat162 lp; lp.x = l0; lp.y = l1;
    hw = *reinterpret_cast<uint32_t*>(&hp);
    lw = *reinterpret_cast<uint32_t*>(&lp);
}

// m16n8k16 bf16 MMA, f32 accumulate in place
__device__ __forceinline__ void mma16816(float* d,
                                         uint32_t a0, uint32_t a1, uint32_t a2, uint32_t a3,
                                         uint32_t b0, uint32_t b1) {
    asm volatile(
        "mma.sync.aligned.m16n8k16.row.col.f32.bf16.bf16.f32 "
        "{%0,%1,%2,%3}, {%4,%5,%6,%7}, {%8,%9}, {%0,%1,%2,%3};"
        : "+f"(d[0]), "+f"(d[1]), "+f"(d[2]), "+f"(d[3])
        : "r"(a0), "r"(a1), "r"(a2), "r"(a3), "r"(b0), "r"(b1));
}

// write 10 state values of node col i, batch g into X hi/lo tiles (bf16)
__device__ __forceinline__ void fill_X(float* sm, int g, int i, const float* v) {
    char* xh = (char*)sm + SM_XHI * 4;
    char* xl = (char*)sm + SM_XLO * 4;
    #pragma unroll
    for (int d = 0; d < HH; d++) {
        int n = g * 10 + d;
        uint32_t off = (uint32_t)(n * (RS * 4) + i * 2);
        __nv_bfloat16 h = __float2bfloat16(v[d]);
        __nv_bfloat16 l = __float2bfloat16(v[d] - __bfloat162float(h));
        *(__nv_bfloat16*)(xh + off) = h;
        *(__nv_bfloat16*)(xl + off) = l;
    }
}

__device__ __forceinline__ void out_head(const float* __restrict__ xr,
                                         const float* __restrict__ nr,
                                         float* __restrict__ op,
                                         float* __restrict__ fp)
{
    unsigned long long fnp[5], xp[5];
    load10(nr, fnp);
    #pragma unroll
    for (int p = 0; p < 5; p++) xp[p] = pack2(xr[2 * p], xr[2 * p + 1]);
    #pragma unroll
    for (int o = 0; o < NOUT; o++) {
        unsigned long long acc = 0ULL;
        #pragma unroll
        for (int q = 0; q < 5; q++) {
            F4U w_;
            w_.v = *(const float4*)(c_wout + o * 20 + 4 * q);
            unsigned long long opnd0 = (2 * q < 5)     ? fnp[2 * q]     : xp[2 * q - 5];
            unsigned long long opnd1 = (2 * q + 1 < 5) ? fnp[2 * q + 1] : xp[2 * q - 4];
            fma2(acc, w_.u[0], opnd0);
            fma2(acc, w_.u[1], opnd1);
        }
        op[o] = tanh_f(c_bout[o] + hsum2(acc));
    }
    #pragma unroll
    for (int h = 0; h < HH; h++) fp[h] = nr[h];
}

__global__ __launch_bounds__(BD, 1)
void ggnn_kernel(const float* __restrict__ x,
                 const float* __restrict__ in_adj,
                 const float* __restrict__ out_adj,
                 float* __restrict__ out0, float* __restrict__ outfn)
{
    extern __shared__ float sm[];
    uint32_t* u32p = (uint32_t*)sm;
    const int tid = threadIdx.x;
    const int wid = tid >> 5;
    const int l   = tid & 31;
    const int rr  = l >> 2;     // groupID
    const int tg  = l & 3;      // thread-in-group

    // ---- stage adjacency as bf16 hi/lo (96x104, zero padded) ----
    for (int idx = tid; idx < 96 * RS; idx += BD) {
        int r = idx / RS, c = idx - r * RS;
        int j0 = 2 * c, j1 = j0 + 1;
        float fi0 = 0.f, fi1 = 0.f, fo0 = 0.f, fo1 = 0.f;
        if (r < NN) {
            if (j0 < NN) { fi0 = in_adj[r * NN + j0]; fo0 = out_adj[r * NN + j0]; }
            if (j1 < NN) { fi1 = in_adj[r * NN + j1]; fo1 = out_adj[r * NN + j1]; }
        }
        uint32_t hw, lw;
        bsplit2(fi0, fi1, hw, lw);
        u32p[SM_AIH + idx] = hw; u32p[SM_AIL + idx] = lw;
        bsplit2(fo0, fo1, hw, lw);
        u32p[SM_AOH + idx] = hw; u32p[SM_AOL + idx] = lw;
    }
    // zero X hi+lo tiles (padding must stay zero)
    for (int idx = tid; idx < 2 * 64 * RS; idx += BD)
        u32p[SM_XHI + idx] = 0;
    __syncthreads();

    const int  i0  = tid / GB;
    const int  i1  = i0 + MHALF;
    const int  g   = tid - i0 * GB;
    const int  b   = blockIdx.x * GB + g;
    const bool act = (tid < MHALF * GB) && (b < B_TOT);

    float* nr0 = sm + SM_ND + (i0 * GB + g) * NROW;
    float* nr1 = sm + SM_ND + (i1 * GB + g) * NROW;

    if (act) {
        const float* xr0 = x + ((size_t)b * NN + i0) * HH;
        const float* xr1 = x + ((size_t)b * NN + i1) * HH;
        float v0[HH], v1[HH];
        #pragma unroll
        for (int h = 0; h < HH; h++) {
            v0[h] = xr0[h]; v1[h] = xr1[h];
            nr0[h] = v0[h]; nr1[h] = v1[h];
        }
        fill_X(sm, g, i0, v0);
        fill_X(sm, g, i1, v1);
    }

    for (int st = 0; st < TSTEPS; st++) {
        __syncthreads();   // X tiles + states ready

        // ---- u3 = w3u . fn (all act threads; overlaps across warps) ----
        float u30[HH], u31[HH];
        if (act) {
            unsigned long long f0[5], f1[5];
            load10(nr0, f0);
            load10(nr1, f1);
            #pragma unroll
            for (int h = 0; h < HH; h++)
                dot10x2c(c_w3u + h * 10, f0, f1, u30[h], u31[h]);
        }

        // ---- tensor-core aggregation: warps 0..5 own 16-row M tiles ----
        if (wid < 6) {
            const uint32_t* xh = u32p + SM_XHI;
            const uint32_t* xl = u32p + SM_XLO;
            #pragma unroll
            for (int dir = 0; dir < 2; dir++) {
                const uint32_t* ah = u32p + (dir ? SM_AOH : SM_AIH);
                const uint32_t* al = u32p + (dir ? SM_AOL : SM_AIL);
                float acc[8][4];
                #pragma unroll
                for (int nt = 0; nt < 8; nt++)
                    #pragma unroll
                    for (int q = 0; q < 4; q++) acc[nt][q] = 0.f;

                #pragma unroll
                for (int kt = 0; kt < 6; kt++) {
                    int ab = (16 * wid + rr) * RS + kt * 8 + tg;
                    uint32_t ah0 = ah[ab],       ah1 = ah[ab + 8 * RS];
                    uint32_t ah2 = ah[ab + 4],   ah3 = ah[ab + 8 * RS + 4];
                    uint32_t al0 = al[ab],       al1 = al[ab + 8 * RS];
                    uint32_t al2 = al[ab + 4],   al3 = al[ab + 8 * RS + 4];
                    #pragma unroll
                    for (int nt = 0; nt < 8; nt++) {
                        int bb = (nt * 8 + rr) * RS + kt * 8 + tg;
                        uint32_t bh0 = xh[bb], bh1 = xh[bb + 4];
                        uint32_t bl0 = xl[bb], bl1 = xl[bb + 4];
                        mma16816(acc[nt], ah0, ah1, ah2, ah3, bh0, bh1);
                        mma16816(acc[nt], ah0, ah1, ah2, ah3, bl0, bl1);
                        mma16816(acc[nt], al0, al1, al2, al3, bh0, bh1);
                    }
                }
                // readback -> av[g][i][dir*10 + d]
                const int ir0 = 16 * wid + rr;
                const int ir1 = ir0 + 8;
                #pragma unroll
                for (int nt = 0; nt < 8; nt++) {
                    int n0 = nt * 8 + tg * 2;
                    int n1 = n0 + 1;
                    if (n0 < 60) {
                        int gg = n0 / 10, dd = n0 - 10 * gg;
                        if (ir0 < NN) sm[SM_AV + (gg * NN + ir0) * 22 + dir * 10 + dd] = acc[nt][0];
                        if (ir1 < NN) sm[SM_AV + (gg * NN + ir1) * 22 + dir * 10 + dd] = acc[nt][2];
                    }
                    if (n1 < 60) {
                        int gg = n1 / 10, dd = n1 - 10 * gg;
                        if (ir0 < NN) sm[SM_AV + (gg * NN + ir0) * 22 + dir * 10 + dd] = acc[nt][1];
                        if (ir1 < NN) sm[SM_AV + (gg * NN + ir1) * 22 + dir * 10 + dd] = acc[nt][3];
                    }
                }
            }
        }
        __syncthreads();   // av ready

        // ---- dense phase ----
        float fnn0[HH], fnn1[HH];
        if (act) {
            unsigned long long av0[HH], av1[HH];
            const float* ar0 = sm + SM_AV + (g * NN + i0) * 22;
            const float* ar1 = sm + SM_AV + (g * NN + i1) * 22;
            #pragma unroll
            for (int p = 0; p < 5; p++) {
                av0[p]     = *(const unsigned long long*)(ar0 + 2 * p);
                av0[5 + p] = *(const unsigned long long*)(ar0 + 10 + 2 * p);
                av1[p]     = *(const unsigned long long*)(ar1 + 2 * p);
                av1[5 + p] = *(const unsigned long long*)(ar1 + 10 + 2 * p);
            }

            float zv0[HH], zv1[HH];
            #pragma unroll
            for (int h = 0; h < HH; h++) {
                float d0, d1;
                dot20x2c(c_w3w + h * 20, av0, av1, d0, d1);
                float bz = c_b3w[h] + c_b3u[h];
                zv0[h] = sigmoid_f(bz + u30[h] + d0);
                zv1[h] = sigmoid_f(bz + u31[h] + d1);
            }

            unsigned long long rf0[5], rf1[5];
            #pragma unroll
            for (int p = 0; p < 5; p++) {
                float da0, da1, db0, db1;
                dot20x2c(c_w4w + (2 * p) * 20,     av0, av1, da0, da1);
                dot20x2c(c_w4w + (2 * p + 1) * 20, av0, av1, db0, db1);
                float bra = c_b4w[2 * p]     + c_b3u[2 * p];      // ref bug: r reuses b3u
                float brb = c_b4w[2 * p + 1] + c_b3u[2 * p + 1];
                float ra0 = sigmoid_f(bra + u30[2 * p]     + da0);
                float rb0 = sigmoid_f(brb + u30[2 * p + 1] + db0);
                float ra1 = sigmoid_f(bra + u31[2 * p]     + da1);
                float rb1 = sigmoid_f(brb + u31[2 * p + 1] + db1);
                rf0[p] = pack2(ra0 * nr0[2 * p], rb0 * nr0[2 * p + 1]);
                rf1[p] = pack2(ra1 * nr1[2 * p], rb1 * nr1[2 * p + 1]);
            }

            #pragma unroll
            for (int h = 0; h < HH; h++) {
                float w0, w1, v0, v1;
                dot20x2c(c_w5w + h * 20, av0, av1, w0, w1);
                dot10x2c(c_w5u + h * 10, rf0, rf1, v0, v1);
                float bh = c_b5w[h] + c_b5u[h];
                float h0 = tanh_f(bh + w0 + v0);
                float h1 = tanh_f(bh + w1 + v1);
                float o0 = nr0[h], o1 = nr1[h];
                fnn0[h] = o0 + zv0[h] * (h0 - o0);
                fnn1[h] = o1 + zv1[h] * (h1 - o1);
            }
        }
        __syncthreads();   // all reads of states/X done

        if (act) {
            #pragma unroll
            for (int h = 0; h < HH; h++) { nr0[h] = fnn0[h]; nr1[h] = fnn1[h]; }
            if (st < TSTEPS - 1) {
                fill_X(sm, g, i0, fnn0);
                fill_X(sm, g, i1, fnn1);
            }
        }
    }

    // ---- output head (reads own state row; no extra sync needed) ----
    if (act) {
        const size_t row0 = (size_t)b * NN + i0;
        const size_t row1 = (size_t)b * NN + i1;
        out_head(x + row0 * HH, nr0, out0 + row0 * NOUT, outfn + row0 * HH);
        out_head(x + row1 * HH, nr1, out0 + row1 * NOUT, outfn + row1 * HH);
    }
}

extern "C" void kernel_launch(void* const* d_in, const int* in_sizes, int n_in,
                              void* d_out, int out_size)
{
    const float* x       = (const float*)d_in[0];
    const float* in_adj  = (const float*)d_in[1];
    const float* out_adj = (const float*)d_in[2];

    cudaMemcpyToSymbolAsync(c_w3w,  d_in[3],  200 * 4, 0, cudaMemcpyDeviceToDevice, 0);
    cudaMemcpyToSymbolAsync(c_b3w,  d_in[4],   10 * 4, 0, cudaMemcpyDeviceToDevice, 0);
    cudaMemcpyToSymbolAsync(c_w3u,  d_in[5],  100 * 4, 0, cudaMemcpyDeviceToDevice, 0);
    cudaMemcpyToSymbolAsync(c_b3u,  d_in[6],   10 * 4, 0, cudaMemcpyDeviceToDevice, 0);
    cudaMemcpyToSymbolAsync(c_w4w,  d_in[7],  200 * 4, 0, cudaMemcpyDeviceToDevice, 0);
    cudaMemcpyToSymbolAsync(c_b4w,  d_in[8],   10 * 4, 0, cudaMemcpyDeviceToDevice, 0);
    cudaMemcpyToSymbolAsync(c_w5w,  d_in[9],  200 * 4, 0, cudaMemcpyDeviceToDevice, 0);
    cudaMemcpyToSymbolAsync(c_b5w,  d_in[10],  10 * 4, 0, cudaMemcpyDeviceToDevice, 0);
    cudaMemcpyToSymbolAsync(c_w5u,  d_in[11], 100 * 4, 0, cudaMemcpyDeviceToDevice, 0);
    cudaMemcpyToSymbolAsync(c_b5u,  d_in[12],  10 * 4, 0, cudaMemcpyDeviceToDevice, 0);
    cudaMemcpyToSymbolAsync(c_wout, d_in[13], 100 * 4, 0, cudaMemcpyDeviceToDevice, 0);
    cudaMemcpyToSymbolAsync(c_bout, d_in[14],   5 * 4, 0, cudaMemcpyDeviceToDevice, 0);

    float* out0  = (float*)d_out;
    float* outfn = out0 + (size_t)B_TOT * NN * NOUT;

    const size_t smbytes = SM_TOTALW * sizeof(float);
    cudaFuncSetAttribute(ggnn_kernel,
                         cudaFuncAttributeMaxDynamicSharedMemorySize,
                         (int)smbytes);

    const int grid = (B_TOT + GB - 1) / GB;
    ggnn_kernel<<<grid, BD, smbytes>>>(x, in_adj, out_adj, out0, outfn);
}

// round 17
// speedup vs baseline: 1.2430x; 1.2430x over previous
#include <cuda_runtime.h>
#include <cuda_bf16.h>
#include <cstdint>

#define B_TOT  8192
#define NN     82
#define HH     10
#define NOUT   5
#define TSTEPS 3
#define GB     6            // batches per block
#define BD     256          // 8 warps; act threads = 41*6 = 246 (2 nodes/thread)
#define NROW   12
#define MHALF  41
#define RS     52           // adjacency/X row stride in 32-bit words (104 bf16)

// ---- shared memory word (float) offsets ----
#define SM_XHI 0                 // X hi : 64 x 52 words
#define SM_XLO 3328              // X lo
#define SM_AV  6656              // av : 6*82*22 floats
#define SM_ND  17480             // node states : 82*6*12 floats
#define SM_TOTALW 23384          // 93536 bytes -> 2 CTAs/SM

// adjacency bf16 hi/lo tiles in global scratch (staged by prep kernel)
// [0]=in_hi [1]=in_lo [2]=out_hi [3]=out_lo
__device__ uint32_t g_adjbuf[4][96 * RS];

// dense weights + biases in constant memory
__constant__ float c_w3w[200];
__constant__ float c_w4w[200];
__constant__ float c_w5w[200];
__constant__ float c_wout[100];
__constant__ float c_w3u[100];
__constant__ float c_w5u[100];
__constant__ float c_b3w[10];
__constant__ float c_b3u[10];
__constant__ float c_b4w[10];
__constant__ float c_b5w[10];
__constant__ float c_b5u[10];
__constant__ float c_bout[5];

union F4U { float4 v; unsigned long long u[2]; float f[4]; };
union F2U { unsigned long long u; float2 f; };

__device__ __forceinline__ unsigned long long pack2(float a, float b) {
    unsigned long long r;
    asm("mov.b64 %0, {%1, %2};" : "=l"(r) : "f"(a), "f"(b));
    return r;
}
__device__ __forceinline__ void fma2(unsigned long long& acc,
                                     unsigned long long a, unsigned long long b) {
    asm("fma.rn.f32x2 %0, %1, %2, %0;" : "+l"(acc) : "l"(a), "l"(b));
}
__device__ __forceinline__ float hsum2(unsigned long long p) {
    F2U u; u.u = p; return u.f.x + u.f.y;
}
__device__ __forceinline__ float sigmoid_f(float v) {
    return __fdividef(1.0f, 1.0f + __expf(-v));
}
__device__ __forceinline__ float tanh_f(float v) {
    return __fdividef(2.0f, 1.0f + __expf(-2.0f * v)) - 1.0f;
}
__device__ __forceinline__ void load10(const float* p, unsigned long long* d) {
    F4U q0, q1; F2U q2;
    q0.v = *(const float4*)(p);
    q1.v = *(const float4*)(p + 4);
    q2.f = *(const float2*)(p + 8);
    d[0] = q0.u[0]; d[1] = q0.u[1]; d[2] = q1.u[0]; d[3] = q1.u[1]; d[4] = q2.u;
}
__device__ __forceinline__ void dot20x2c(const float* wrow,
                                         const unsigned long long* av0,
                                         const unsigned long long* av1,
                                         float& r0, float& r1) {
    unsigned long long a0 = 0ULL, a1 = 0ULL;
    #pragma unroll
    for (int q = 0; q < 5; q++) {
        F4U w_;
        w_.v = *(const float4*)(wrow + 4 * q);
        fma2(a0, w_.u[0], av0[2 * q]);
        fma2(a0, w_.u[1], av0[2 * q + 1]);
        fma2(a1, w_.u[0], av1[2 * q]);
        fma2(a1, w_.u[1], av1[2 * q + 1]);
    }
    r0 = hsum2(a0);
    r1 = hsum2(a1);
}
__device__ __forceinline__ void dot10x2c(const float* urow,
                                         const unsigned long long* v0,
                                         const unsigned long long* v1,
                                         float& r0, float& r1) {
    unsigned long long a0 = 0ULL, a1 = 0ULL;
    #pragma unroll
    for (int p = 0; p < 5; p++) {
        F2U w; w.f = *(const float2*)(urow + 2 * p);
        fma2(a0, w.u, v0[p]);
        fma2(a1, w.u, v1[p]);
    }
    r0 = hsum2(a0);
    r1 = hsum2(a1);
}

__device__ __forceinline__ void bsplit2(float f0, float f1, uint32_t& hw, uint32_t& lw) {
    __nv_bfloat16 h0 = __float2bfloat16(f0);
    __nv_bfloat16 h1 = __float2bfloat16(f1);
    __nv_bfloat16 l0 = __float2bfloat16(f0 - __bfloat162float(h0));
    __nv_bfloat16 l1 = __float2bfloat16(f1 - __bfloat162float(h1));
    __nv_bfloat162 hp; hp.x = h0; hp.y = h1;
    __nv_bfloat162 lp; lp.x = l0; lp.y = l1;
    hw = *reinterpret_cast<uint32_t*>(&hp);
    lw = *reinterpret_cast<uint32_t*>(&lp);
}

// m16n8k16 bf16 MMA, f32 accumulate in place
__device__ __forceinline__ void mma16816(float* d,
                                         uint32_t a0, uint32_t a1, uint32_t a2, uint32_t a3,
                                         uint32_t b0, uint32_t b1) {
    asm volatile(
        "mma.sync.aligned.m16n8k16.row.col.f32.bf16.bf16.f32 "
        "{%0,%1,%2,%3}, {%4,%5,%6,%7}, {%8,%9}, {%0,%1,%2,%3};"
        : "+f"(d[0]), "+f"(d[1]), "+f"(d[2]), "+f"(d[3])
        : "r"(a0), "r"(a1), "r"(a2), "r"(a3), "r"(b0), "r"(b1));
}

// write 10 state values of node col i, batch g into X hi/lo tiles (bf16)
__device__ __forceinline__ void fill_X(float* sm, int g, int i, const float* v) {
    char* xh = (char*)sm + SM_XHI * 4;
    char* xl = (char*)sm + SM_XLO * 4;
    #pragma unroll
    for (int d = 0; d < HH; d++) {
        int n = g * 10 + d;
        uint32_t off = (uint32_t)(n * (RS * 4) + i * 2);
        __nv_bfloat16 h = __float2bfloat16(v[d]);
        __nv_bfloat16 l = __float2bfloat16(v[d] - __bfloat162float(h));
        *(__nv_bfloat16*)(xh + off) = h;
        *(__nv_bfloat16*)(xl + off) = l;
    }
}

__device__ __forceinline__ void out_head(const float* __restrict__ xr,
                                         const float* __restrict__ nr,
                                         float* __restrict__ op,
                                         float* __restrict__ fp)
{
    unsigned long long fnp[5], xp[5];
    load10(nr, fnp);
    #pragma unroll
    for (int p = 0; p < 5; p++) xp[p] = pack2(xr[2 * p], xr[2 * p + 1]);
    #pragma unroll
    for (int o = 0; o < NOUT; o++) {
        unsigned long long acc = 0ULL;
        #pragma unroll
        for (int q = 0; q < 5; q++) {
            F4U w_;
            w_.v = *(const float4*)(c_wout + o * 20 + 4 * q);
            unsigned long long opnd0 = (2 * q < 5)     ? fnp[2 * q]     : xp[2 * q - 5];
            unsigned long long opnd1 = (2 * q + 1 < 5) ? fnp[2 * q + 1] : xp[2 * q - 4];
            fma2(acc, w_.u[0], opnd0);
            fma2(acc, w_.u[1], opnd1);
        }
        op[o] = tanh_f(c_bout[o] + hsum2(acc));
    }
    #pragma unroll
    for (int h = 0; h < HH; h++) fp[h] = nr[h];
}

// ---- prep kernel: stage adjacency bf16 hi/lo tiles into global scratch ----
__global__ void adj_prep_kernel(const float* __restrict__ in_adj,
                                const float* __restrict__ out_adj)
{
    int idx = blockIdx.x * blockDim.x + threadIdx.x;
    if (idx >= 96 * RS) return;
    int r = idx / RS, c = idx - r * RS;
    int j0 = 2 * c, j1 = j0 + 1;
    float fi0 = 0.f, fi1 = 0.f, fo0 = 0.f, fo1 = 0.f;
    if (r < NN) {
        if (j0 < NN) { fi0 = in_adj[r * NN + j0]; fo0 = out_adj[r * NN + j0]; }
        if (j1 < NN) { fi1 = in_adj[r * NN + j1]; fo1 = out_adj[r * NN + j1]; }
    }
    uint32_t hw, lw;
    bsplit2(fi0, fi1, hw, lw);
    g_adjbuf[0][idx] = hw; g_adjbuf[1][idx] = lw;
    bsplit2(fo0, fo1, hw, lw);
    g_adjbuf[2][idx] = hw; g_adjbuf[3][idx] = lw;
}

__global__ __launch_bounds__(BD, 2)
void ggnn_kernel(const float* __restrict__ x,
                 float* __restrict__ out0, float* __restrict__ outfn)
{
    extern __shared__ float sm[];
    uint32_t* u32p = (uint32_t*)sm;
    const int tid = threadIdx.x;
    const int wid = tid >> 5;
    const int l   = tid & 31;
    const int rr  = l >> 2;     // groupID
    const int tg  = l & 3;      // thread-in-group

    // zero X hi+lo tiles (padding must stay zero)
    for (int idx = tid; idx < 2 * 64 * RS; idx += BD)
        u32p[SM_XHI + idx] = 0;
    __syncthreads();

    const int  i0  = tid / GB;
    const int  i1  = i0 + MHALF;
    const int  g   = tid - i0 * GB;
    const int  b   = blockIdx.x * GB + g;
    const bool act = (tid < MHALF * GB) && (b < B_TOT);

    float* nr0 = sm + SM_ND + (i0 * GB + g) * NROW;
    float* nr1 = sm + SM_ND + (i1 * GB + g) * NROW;

    if (act) {
        const float* xr0 = x + ((size_t)b * NN + i0) * HH;
        const float* xr1 = x + ((size_t)b * NN + i1) * HH;
        float v0[HH], v1[HH];
        #pragma unroll
        for (int h = 0; h < HH; h++) {
            v0[h] = xr0[h]; v1[h] = xr1[h];
            nr0[h] = v0[h]; nr1[h] = v1[h];
        }
        fill_X(sm, g, i0, v0);
        fill_X(sm, g, i1, v1);
    }

    for (int st = 0; st < TSTEPS; st++) {
        __syncthreads();   // X tiles + states ready

        // ---- u3 = w3u . fn (all act threads) ----
        float u30[HH], u31[HH];
        if (act) {
            unsigned long long f0[5], f1[5];
            load10(nr0, f0);
            load10(nr1, f1);
            #pragma unroll
            for (int h = 0; h < HH; h++)
                dot10x2c(c_w3u + h * 10, f0, f1, u30[h], u31[h]);
        }

        // ---- tensor-core aggregation: warps 0..5 own 16-row M tiles ----
        if (wid < 6) {
            const uint32_t* xh = u32p + SM_XHI;
            const uint32_t* xl = u32p + SM_XLO;
            #pragma unroll
            for (int dir = 0; dir < 2; dir++) {
                const uint32_t* __restrict__ ah = g_adjbuf[dir ? 2 : 0];
                const uint32_t* __restrict__ al = g_adjbuf[dir ? 3 : 1];
                float acc[8][4];
                #pragma unroll
                for (int nt = 0; nt < 8; nt++)
                    #pragma unroll
                    for (int q = 0; q < 4; q++) acc[nt][q] = 0.f;

                #pragma unroll
                for (int kt = 0; kt < 6; kt++) {
                    int ab = (16 * wid + rr) * RS + kt * 8 + tg;
                    uint32_t ah0 = __ldg(ah + ab),          ah1 = __ldg(ah + ab + 8 * RS);
                    uint32_t ah2 = __ldg(ah + ab + 4),      ah3 = __ldg(ah + ab + 8 * RS + 4);
                    uint32_t al0 = __ldg(al + ab),          al1 = __ldg(al + ab + 8 * RS);
                    uint32_t al2 = __ldg(al + ab + 4),      al3 = __ldg(al + ab + 8 * RS + 4);
                    #pragma unroll
                    for (int nt = 0; nt < 8; nt++) {
                        int bb = (nt * 8 + rr) * RS + kt * 8 + tg;
                        uint32_t bh0 = xh[bb], bh1 = xh[bb + 4];
                        uint32_t bl0 = xl[bb], bl1 = xl[bb + 4];
                        mma16816(acc[nt], ah0, ah1, ah2, ah3, bh0, bh1);
                        mma16816(acc[nt], ah0, ah1, ah2, ah3, bl0, bl1);
                        mma16816(acc[nt], al0, al1, al2, al3, bh0, bh1);
                    }
                }
                // readback -> av[g][i][dir*10 + d]
                const int ir0 = 16 * wid + rr;
                const int ir1 = ir0 + 8;
                #pragma unroll
                for (int nt = 0; nt < 8; nt++) {
                    int n0 = nt * 8 + tg * 2;
                    int n1 = n0 + 1;
                    if (n0 < 60) {
                        int gg = n0 / 10, dd = n0 - 10 * gg;
                        if (ir0 < NN) sm[SM_AV + (gg * NN + ir0) * 22 + dir * 10 + dd] = acc[nt][0];
                        if (ir1 < NN) sm[SM_AV + (gg * NN + ir1) * 22 + dir * 10 + dd] = acc[nt][2];
                    }
                    if (n1 < 60) {
                        int gg = n1 / 10, dd = n1 - 10 * gg;
                        if (ir0 < NN) sm[SM_AV + (gg * NN + ir0) * 22 + dir * 10 + dd] = acc[nt][1];
                        if (ir1 < NN) sm[SM_AV + (gg * NN + ir1) * 22 + dir * 10 + dd] = acc[nt][3];
                    }
                }
            }
        }
        __syncthreads();   // av ready

        // ---- dense phase ----
        float fnn0[HH], fnn1[HH];
        if (act) {
            unsigned long long av0[HH], av1[HH];
            const float* ar0 = sm + SM_AV + (g * NN + i0) * 22;
            const float* ar1 = sm + SM_AV + (g * NN + i1) * 22;
            #pragma unroll
            for (int p = 0; p < 5; p++) {
                av0[p]     = *(const unsigned long long*)(ar0 + 2 * p);
                av0[5 + p] = *(const unsigned long long*)(ar0 + 10 + 2 * p);
                av1[p]     = *(const unsigned long long*)(ar1 + 2 * p);
                av1[5 + p] = *(const unsigned long long*)(ar1 + 10 + 2 * p);
            }

            float zv0[HH], zv1[HH];
            #pragma unroll
            for (int h = 0; h < HH; h++) {
                float d0, d1;
                dot20x2c(c_w3w + h * 20, av0, av1, d0, d1);
                float bz = c_b3w[h] + c_b3u[h];
                zv0[h] = sigmoid_f(bz + u30[h] + d0);
                zv1[h] = sigmoid_f(bz + u31[h] + d1);
            }

            unsigned long long rf0[5], rf1[5];
            #pragma unroll
            for (int p = 0; p < 5; p++) {
                float da0, da1, db0, db1;
                dot20x2c(c_w4w + (2 * p) * 20,     av0, av1, da0, da1);
                dot20x2c(c_w4w + (2 * p + 1) * 20, av0, av1, db0, db1);
                float bra = c_b4w[2 * p]     + c_b3u[2 * p];      // ref bug: r reuses b3u
                float brb = c_b4w[2 * p + 1] + c_b3u[2 * p + 1];
                float ra0 = sigmoid_f(bra + u30[2 * p]     + da0);
                float rb0 = sigmoid_f(brb + u30[2 * p + 1] + db0);
                float ra1 = sigmoid_f(bra + u31[2 * p]     + da1);
                float rb1 = sigmoid_f(brb + u31[2 * p + 1] + db1);
                rf0[p] = pack2(ra0 * nr0[2 * p], rb0 * nr0[2 * p + 1]);
                rf1[p] = pack2(ra1 * nr1[2 * p], rb1 * nr1[2 * p + 1]);
            }

            #pragma unroll
            for (int h = 0; h < HH; h++) {
                float w0, w1, v0, v1;
                dot20x2c(c_w5w + h * 20, av0, av1, w0, w1);
                dot10x2c(c_w5u + h * 10, rf0, rf1, v0, v1);
                float bh = c_b5w[h] + c_b5u[h];
                float h0 = tanh_f(bh + w0 + v0);
                float h1 = tanh_f(bh + w1 + v1);
                float o0 = nr0[h], o1 = nr1[h];
                fnn0[h] = o0 + zv0[h] * (h0 - o0);
                fnn1[h] = o1 + zv1[h] * (h1 - o1);
            }
        }
        __syncthreads();   // all reads of states/X/av done

        if (act) {
            #pragma unroll
            for (int h = 0; h < HH; h++) { nr0[h] = fnn0[h]; nr1[h] = fnn1[h]; }
            if (st < TSTEPS - 1) {
                fill_X(sm, g, i0, fnn0);
                fill_X(sm, g, i1, fnn1);
            }
        }
    }

    // ---- output head ----
    if (act) {
        const size_t row0 = (size_t)b * NN + i0;
        const size_t row1 = (size_t)b * NN + i1;
        out_head(x + row0 * HH, nr0, out0 + row0 * NOUT, outfn + row0 * HH);
        out_head(x + row1 * HH, nr1, out0 + row1 * NOUT, outfn + row1 * HH);
    }
}

extern "C" void kernel_launch(void* const* d_in, const int* in_sizes, int n_in,
                              void* d_out, int out_size)
{
    const float* x       = (const float*)d_in[0];
    const float* in_adj  = (const float*)d_in[1];
    const float* out_adj = (const float*)d_in[2];

    cudaMemcpyToSymbolAsync(c_w3w,  d_in[3],  200 * 4, 0, cudaMemcpyDeviceToDevice, 0);
    cudaMemcpyToSymbolAsync(c_b3w,  d_in[4],   10 * 4, 0, cudaMemcpyDeviceToDevice, 0);
    cudaMemcpyToSymbolAsync(c_w3u,  d_in[5],  100 * 4, 0, cudaMemcpyDeviceToDevice, 0);
    cudaMemcpyToSymbolAsync(c_b3u,  d_in[6],   10 * 4, 0, cudaMemcpyDeviceToDevice, 0);
    cudaMemcpyToSymbolAsync(c_w4w,  d_in[7],  200 * 4, 0, cudaMemcpyDeviceToDevice, 0);
    cudaMemcpyToSymbolAsync(c_b4w,  d_in[8],   10 * 4, 0, cudaMemcpyDeviceToDevice, 0);
    cudaMemcpyToSymbolAsync(c_w5w,  d_in[9],  200 * 4, 0, cudaMemcpyDeviceToDevice, 0);
    cudaMemcpyToSymbolAsync(c_b5w,  d_in[10],  10 * 4, 0, cudaMemcpyDeviceToDevice, 0);
    cudaMemcpyToSymbolAsync(c_w5u,  d_in[11], 100 * 4, 0, cudaMemcpyDeviceToDevice, 0);
    cudaMemcpyToSymbolAsync(c_b5u,  d_in[12],  10 * 4, 0, cudaMemcpyDeviceToDevice, 0);
    cudaMemcpyToSymbolAsync(c_wout, d_in[13], 100 * 4, 0, cudaMemcpyDeviceToDevice, 0);
    cudaMemcpyToSymbolAsync(c_bout, d_in[14],   5 * 4, 0, cudaMemcpyDeviceToDevice, 0);

    float* out0  = (float*)d_out;
    float* outfn = out0 + (size_t)B_TOT * NN * NOUT;

    // stage adjacency bf16 tiles (same stream -> ordered before main kernel)
    adj_prep_kernel<<<(96 * RS + 255) / 256, 256>>>(in_adj, out_adj);

    const size_t smbytes = SM_TOTALW * sizeof(float);
    cudaFuncSetAttribute(ggnn_kernel,
                         cudaFuncAttributeMaxDynamicSharedMemorySize,
                         (int)smbytes);

    const int grid = (B_TOT + GB - 1) / GB;
    ggnn_kernel<<<grid, BD, smbytes>>>(x, out0, outfn);
}